// round 10
// baseline (speedup 1.0000x reference)
#include <cuda_runtime.h>
#include <cuda_bf16.h>
#include <math.h>

#define BATCH  8192
#define NNZ    32
#define FT_IN  40960
#define FT_OUT 512
#define NTHREADS 256   // one batch row per CTA: 2 k-split groups x (2 halves x 64 col slots)
#define KSPLIT 2
#define KPER  (NNZ / KSPLIT)   // 16 indices per thread

// 40 MB bf16 copy of the feature table (static device scratch — no runtime alloc)
__device__ __nv_bfloat16 g_wft[FT_IN * FT_OUT];

// ---------------- Kernel 1: f32 -> bf16 table conversion (streaming) -------------
__global__ __launch_bounds__(256)
void convert_kernel(const float4* __restrict__ W_ft)
{
    const int i = blockIdx.x * 256 + threadIdx.x;   // group of 8 floats
    const float4 a = __ldcs(&W_ft[2 * i]);
    const float4 b = __ldcs(&W_ft[2 * i + 1]);
    __nv_bfloat162 p0 = __floats2bfloat162_rn(a.x, a.y);
    __nv_bfloat162 p1 = __floats2bfloat162_rn(a.z, a.w);
    __nv_bfloat162 p2 = __floats2bfloat162_rn(b.x, b.y);
    __nv_bfloat162 p3 = __floats2bfloat162_rn(b.z, b.w);
    uint4 o;
    o.x = *(unsigned*)&p0;  o.y = *(unsigned*)&p1;
    o.z = *(unsigned*)&p2;  o.w = *(unsigned*)&p3;
    ((uint4*)g_wft)[i] = o;
}

// f32 view of packed bf16 pair: low elem = shift; high elem = raw word (junk low
// mantissa bits perturb by <2^-8 relative — same order as bf16 rounding itself)
__device__ __forceinline__ float bf_lo(unsigned w) { return __int_as_float((int)(w << 16)); }
__device__ __forceinline__ float bf_hi(unsigned w) { return __uint_as_float(w); }

// ---------------- Kernel 2: sparse gather + MLP head from bf16 table -------------
__global__ __launch_bounds__(NTHREADS)
void nnue_fwd_kernel(const int*    __restrict__ stm_idx,    // [BATCH, NNZ]
                     const int*    __restrict__ nstm_idx,   // [BATCH, NNZ]
                     const float*  __restrict__ values,     // [BATCH, NNZ]
                     const float4* __restrict__ b_ft,       // [FT_OUT]
                     const float4* __restrict__ W_out,      // [2*FT_OUT]
                     const float*  __restrict__ b_out,      // [1]
                     float*        __restrict__ out)        // [BATCH]
{
    const int t    = threadIdx.x;
    const int ks   = t >> 7;               // k-split group 0/1
    const int lt   = t & 127;              // lane within group
    const int half = lt >> 6;              // 0 = stm, 1 = nstm
    const int c    = lt & 63;              // uint4 (8-col) slot 0..63
    const int b    = blockIdx.x;

    // packed per-k record: {row offset in uint4 units, value bits (f32)}
    __shared__ int2  s_ov[2 * NNZ];        // [stm 0..31 | nstm 0..31]
    __shared__ float s_part[8][128];       // ks=1 partial sums, conflict-free layout
    __shared__ float s_red[4];

    if (t < NNZ) {
        const float v = __ldcs(&values[b * NNZ + t]);
        const int vb = __float_as_int(v);
        s_ov[t]       = make_int2(__ldcs(&stm_idx [b * NNZ + t]) * (FT_OUT / 8), vb);
        s_ov[NNZ + t] = make_int2(__ldcs(&nstm_idx[b * NNZ + t]) * (FT_OUT / 8), vb);
    }
    __syncthreads();

    const int2*  my  = &s_ov[half * NNZ + ks * KPER];
    const uint4* tab = (const uint4*)g_wft + c;    // row stride = FT_OUT/8 uint4

    float acc[8] = {0.f, 0.f, 0.f, 0.f, 0.f, 0.f, 0.f, 0.f};

    #pragma unroll
    for (int k = 0; k < KPER; k++) {
        const int2  ov = my[k];
        const uint4 w  = __ldg(tab + ov.x);
        const float v  = __int_as_float(ov.y);
        acc[0] = fmaf(v, bf_lo(w.x), acc[0]);
        acc[1] = fmaf(v, bf_hi(w.x), acc[1]);
        acc[2] = fmaf(v, bf_lo(w.y), acc[2]);
        acc[3] = fmaf(v, bf_hi(w.y), acc[3]);
        acc[4] = fmaf(v, bf_lo(w.z), acc[4]);
        acc[5] = fmaf(v, bf_hi(w.z), acc[5]);
        acc[6] = fmaf(v, bf_lo(w.w), acc[6]);
        acc[7] = fmaf(v, bf_hi(w.w), acc[7]);
    }

    // combine k-split partials: ks=1 publishes, ks=0 folds in
    if (ks == 1) {
        #pragma unroll
        for (int i = 0; i < 8; i++) s_part[i][lt] = acc[i];
    }
    __syncthreads();

    float p = 0.f;
    if (ks == 0) {
        #pragma unroll
        for (int i = 0; i < 8; i++) acc[i] += s_part[i][lt];

        // bias + clamp [0,1] + dot with matching W_out half (hidden = [stm|nstm])
        const float4 bb0 = __ldg(&b_ft[2 * c]);
        const float4 bb1 = __ldg(&b_ft[2 * c + 1]);
        const float4 wo0 = __ldg(&W_out[half * (FT_OUT / 4) + 2 * c]);
        const float4 wo1 = __ldg(&W_out[half * (FT_OUT / 4) + 2 * c + 1]);
        const float bbv[8] = {bb0.x, bb0.y, bb0.z, bb0.w, bb1.x, bb1.y, bb1.z, bb1.w};
        const float wov[8] = {wo0.x, wo0.y, wo0.z, wo0.w, wo1.x, wo1.y, wo1.z, wo1.w};
        #pragma unroll
        for (int i = 0; i < 8; i++) {
            const float h = fminf(fmaxf(acc[i] + bbv[i], 0.f), 1.f);
            p = fmaf(h, wov[i], p);
        }
        // warp reduce (warps 0-3 are entirely ks=0)
        #pragma unroll
        for (int off = 16; off > 0; off >>= 1)
            p += __shfl_xor_sync(0xFFFFFFFFu, p, off);
        if ((lt & 31) == 0) s_red[lt >> 5] = p;
    }
    __syncthreads();

    if (t == 0) {
        float s = s_red[0] + s_red[1] + s_red[2] + s_red[3] + __ldg(b_out);
        out[b] = 1.0f / (1.0f + expf(-s));
    }
}

extern "C" void kernel_launch(void* const* d_in, const int* in_sizes, int n_in,
                              void* d_out, int out_size)
{
    const int*    stm_idx  = (const int*)   d_in[0];
    const int*    nstm_idx = (const int*)   d_in[1];
    const float*  values   = (const float*) d_in[2];
    const float4* W_ft     = (const float4*)d_in[3];
    const float4* b_ft     = (const float4*)d_in[4];
    const float4* W_out    = (const float4*)d_in[5];
    const float*  b_out    = (const float*) d_in[6];
    float*        out      = (float*)       d_out;

    // 20,971,520 floats / 8 per thread / 256 threads = 10240 blocks
    convert_kernel<<<(FT_IN * FT_OUT) / (8 * 256), 256>>>(W_ft);
    nnue_fwd_kernel<<<BATCH, NTHREADS>>>(stm_idx, nstm_idx, values,
                                         b_ft, W_out, b_out, out);
}

// round 11
// speedup vs baseline: 1.1094x; 1.1094x over previous
#include <cuda_runtime.h>
#include <math.h>

#define BATCH  8192
#define NNZ    32
#define FT_IN  40960
#define FT_OUT 512
#define ROWS_PER_CTA 2
#define NTHREADS 256   // 128 threads per batch row: 64 stm + 64 nstm, 8 cols each

// int8 quantized feature table (20 MB) + per-row f32 scales (static scratch)
__device__ unsigned g_wq[FT_IN * FT_OUT / 4];   // biased uint8, 4 per word
__device__ float    g_scale[FT_IN];

// ---------------- Kernel 1: f32 -> int8 per-row quantization (one warp/row) ------
__global__ __launch_bounds__(256)
void quant_kernel(const float4* __restrict__ W_ft)
{
    const int warp = (blockIdx.x * 256 + threadIdx.x) >> 5;   // feature row
    const int lane = threadIdx.x & 31;

    const float4* rowp = W_ft + warp * (FT_OUT / 4);
    float4 x[4];
    #pragma unroll
    for (int j = 0; j < 4; j++) x[j] = __ldcs(&rowp[lane + 32 * j]);

    float m = 0.f;
    #pragma unroll
    for (int j = 0; j < 4; j++) {
        m = fmaxf(m, fmaxf(fmaxf(fabsf(x[j].x), fabsf(x[j].y)),
                           fmaxf(fabsf(x[j].z), fabsf(x[j].w))));
    }
    #pragma unroll
    for (int off = 16; off > 0; off >>= 1)
        m = fmaxf(m, __shfl_xor_sync(0xFFFFFFFFu, m, off));

    const float inv = (m > 0.f) ? 127.f / m : 0.f;

    #pragma unroll
    for (int j = 0; j < 4; j++) {
        const float* e = &x[j].x;
        unsigned w = 0;
        #pragma unroll
        for (int i = 0; i < 4; i++) {
            int q = __float2int_rn(e[i] * inv);
            q = min(max(q, -127), 127);
            w |= (unsigned)(q + 128) << (8 * i);
        }
        g_wq[warp * (FT_OUT / 4) + lane + 32 * j] = w;
    }
    if (lane == 0) g_scale[warp] = m * (1.f / 127.f);
}

// ---------------- Kernel 2: int8 sparse gather + MLP head ------------------------
__global__ __launch_bounds__(NTHREADS)
void nnue_fwd_kernel(const int*    __restrict__ stm_idx,    // [BATCH, NNZ]
                     const int*    __restrict__ nstm_idx,   // [BATCH, NNZ]
                     const float*  __restrict__ values,     // [BATCH, NNZ]
                     const float4* __restrict__ b_ft,       // [FT_OUT]
                     const float4* __restrict__ W_out,      // [2*FT_OUT]
                     const float*  __restrict__ b_out,      // [1]
                     float*        __restrict__ out)        // [BATCH]
{
    const int t    = threadIdx.x;
    const int r    = t >> 7;               // row within CTA (0/1)
    const int lt   = t & 127;              // lane within row group
    const int half = lt >> 6;              // 0 = stm, 1 = nstm
    const int c    = lt & 63;              // uint2 (8-col) slot 0..63
    const int b    = blockIdx.x * ROWS_PER_CTA + r;

    // packed per-k record: {row offset in uint2 units, vs' = v*scale/256 bits}
    __shared__ int2  s_ov[ROWS_PER_CTA][2 * NNZ];
    __shared__ float s_red[NTHREADS / 32];

    if (lt < NNZ) {
        const int   is = __ldcs(&stm_idx [b * NNZ + lt]);
        const int   in = __ldcs(&nstm_idx[b * NNZ + lt]);
        const float v  = __ldcs(&values  [b * NNZ + lt]);
        const float vs_s = v * __ldg(&g_scale[is]) * (1.f / 256.f);
        const float vs_n = v * __ldg(&g_scale[in]) * (1.f / 256.f);
        s_ov[r][lt]       = make_int2(is * (FT_OUT / 8), __float_as_int(vs_s));
        s_ov[r][NNZ + lt] = make_int2(in * (FT_OUT / 8), __float_as_int(vs_n));
    }
    __syncthreads();

    const int2*  my  = &s_ov[r][half * NNZ];
    const uint2* tab = (const uint2*)g_wq + c;     // row stride = FT_OUT/8 uint2

    float acc[8] = {0.f, 0.f, 0.f, 0.f, 0.f, 0.f, 0.f, 0.f};
    float sv = 0.f;

    #pragma unroll
    for (int k = 0; k < NNZ; k++) {
        const int2  ov = my[k];
        const uint2 w  = __ldg(tab + ov.x);
        const float vs = __int_as_float(ov.y);
        sv += vs;
        // magic-bias decode: f = 2^23 + 256*u  (u = biased uint8, safely in mantissa)
        #pragma unroll
        for (int j = 0; j < 4; j++) {
            const float f = __uint_as_float(__byte_perm(w.x, 0x4B000000u, 0x7404 + (j << 4)));
            acc[j] = fmaf(f, vs, acc[j]);
        }
        #pragma unroll
        for (int j = 0; j < 4; j++) {
            const float f = __uint_as_float(__byte_perm(w.y, 0x4B000000u, 0x7404 + (j << 4)));
            acc[4 + j] = fmaf(f, vs, acc[4 + j]);
        }
    }

    // remove accumulated magic bias: W_i = acc_i - (2^23 + 2^15) * sum(vs')
    // (2^23*sv from the magic constant, 2^15*sv from the u = q+128 bias)
    float mres[8];
    #pragma unroll
    for (int i = 0; i < 8; i++) mres[i] = fmaf(-8421376.f, sv, acc[i]);

    // bias + clamp [0,1] + dot with matching W_out half (hidden = [stm | nstm])
    const float4 bb0 = __ldg(&b_ft[2 * c]);
    const float4 bb1 = __ldg(&b_ft[2 * c + 1]);
    const float4 wo0 = __ldg(&W_out[half * (FT_OUT / 4) + 2 * c]);
    const float4 wo1 = __ldg(&W_out[half * (FT_OUT / 4) + 2 * c + 1]);
    const float bbv[8] = {bb0.x, bb0.y, bb0.z, bb0.w, bb1.x, bb1.y, bb1.z, bb1.w};
    const float wov[8] = {wo0.x, wo0.y, wo0.z, wo0.w, wo1.x, wo1.y, wo1.z, wo1.w};
    float p = 0.f;
    #pragma unroll
    for (int i = 0; i < 8; i++) {
        const float h = fminf(fmaxf(mres[i] + bbv[i], 0.f), 1.f);
        p = fmaf(h, wov[i], p);
    }

    // warp reduce (each warp = 32 threads of one half-row slice)
    #pragma unroll
    for (int off = 16; off > 0; off >>= 1)
        p += __shfl_xor_sync(0xFFFFFFFFu, p, off);

    if ((t & 31) == 0) s_red[t >> 5] = p;
    __syncthreads();

    // warps 0-3 belong to row 0, warps 4-7 to row 1
    if ((t & 127) == 0) {
        const int w0 = r * 4;
        float s = s_red[w0] + s_red[w0 + 1] + s_red[w0 + 2] + s_red[w0 + 3]
                + __ldg(b_out);
        out[b] = 1.0f / (1.0f + expf(-s));
    }
}

extern "C" void kernel_launch(void* const* d_in, const int* in_sizes, int n_in,
                              void* d_out, int out_size)
{
    const int*    stm_idx  = (const int*)   d_in[0];
    const int*    nstm_idx = (const int*)   d_in[1];
    const float*  values   = (const float*) d_in[2];
    const float4* W_ft     = (const float4*)d_in[3];
    const float4* b_ft     = (const float4*)d_in[4];
    const float4* W_out    = (const float4*)d_in[5];
    const float*  b_out    = (const float*) d_in[6];
    float*        out      = (float*)       d_out;

    // one warp per feature row: 40960 warps / 8 per CTA = 5120 CTAs
    quant_kernel<<<FT_IN / 8, 256>>>(W_ft);
    nnue_fwd_kernel<<<BATCH / ROWS_PER_CTA, NTHREADS>>>(stm_idx, nstm_idx, values,
                                                        b_ft, W_out, b_out, out);
}